// round 1
// baseline (speedup 1.0000x reference)
#include <cuda_runtime.h>

#define T_SEQ 4096
#define C_DIM 1024
#define NHEAD 16
#define DHEAD 64

// Scratch (static __device__ — no allocation allowed)
__device__ float g_q[T_SEQ * C_DIM];
__device__ float g_k[T_SEQ * C_DIM];
__device__ float g_v[T_SEQ * C_DIM];
__device__ float g_y[T_SEQ * C_DIM];

// ---------------------------------------------------------------------------
// GEMM (NT): C[M,N] = A[M,K] @ B[N,K]^T + bias[N]
// 128x128 tile, BK=16, 256 threads, 8x8 per thread.
// ---------------------------------------------------------------------------
__global__ __launch_bounds__(256, 2)
void gemm_nt_bias(const float* __restrict__ A, const float* __restrict__ B,
                  const float* __restrict__ bias, float* __restrict__ C,
                  int M, int N, int K)
{
    __shared__ float As[16][132];   // [k][m], pad 132 to de-conflict transposed stores
    __shared__ float Bs[16][132];   // [k][n]

    const int tid = threadIdx.x;
    const int tx  = tid & 15;       // n-group
    const int ty  = tid >> 4;       // m-group
    const int m0  = blockIdx.y * 128;
    const int n0  = blockIdx.x * 128;

    float acc[8][8];
#pragma unroll
    for (int i = 0; i < 8; i++)
#pragma unroll
        for (int j = 0; j < 8; j++) acc[i][j] = 0.f;

    for (int k0 = 0; k0 < K; k0 += 16) {
#pragma unroll
        for (int i = 0; i < 2; i++) {
            int f  = tid + i * 256;         // 512 float4s per tile
            int r  = f >> 2;                // row within tile (0..127)
            int kc = (f & 3) << 2;          // k offset (0,4,8,12)
            float4 a4 = *(const float4*)(A + (size_t)(m0 + r) * K + k0 + kc);
            As[kc + 0][r] = a4.x; As[kc + 1][r] = a4.y;
            As[kc + 2][r] = a4.z; As[kc + 3][r] = a4.w;
            float4 b4 = *(const float4*)(B + (size_t)(n0 + r) * K + k0 + kc);
            Bs[kc + 0][r] = b4.x; Bs[kc + 1][r] = b4.y;
            Bs[kc + 2][r] = b4.z; Bs[kc + 3][r] = b4.w;
        }
        __syncthreads();
#pragma unroll
        for (int kk = 0; kk < 16; kk++) {
            float a[8], b[8];
            *(float4*)&a[0] = *(const float4*)&As[kk][ty * 8];
            *(float4*)&a[4] = *(const float4*)&As[kk][ty * 8 + 4];
            *(float4*)&b[0] = *(const float4*)&Bs[kk][tx * 8];
            *(float4*)&b[4] = *(const float4*)&Bs[kk][tx * 8 + 4];
#pragma unroll
            for (int i = 0; i < 8; i++)
#pragma unroll
                for (int j = 0; j < 8; j++)
                    acc[i][j] += a[i] * b[j];
        }
        __syncthreads();
    }

    float bv[8];
#pragma unroll
    for (int j = 0; j < 8; j++) bv[j] = bias[n0 + tx * 8 + j];

#pragma unroll
    for (int i = 0; i < 8; i++) {
        int m = m0 + ty * 8 + i;
        float4 o0, o1;
        o0.x = acc[i][0] + bv[0]; o0.y = acc[i][1] + bv[1];
        o0.z = acc[i][2] + bv[2]; o0.w = acc[i][3] + bv[3];
        o1.x = acc[i][4] + bv[4]; o1.y = acc[i][5] + bv[5];
        o1.z = acc[i][6] + bv[6]; o1.w = acc[i][7] + bv[7];
        *(float4*)(C + (size_t)m * N + n0 + tx * 8)     = o0;
        *(float4*)(C + (size_t)m * N + n0 + tx * 8 + 4) = o1;
    }
}

// ---------------------------------------------------------------------------
// Flash attention, fp32. CTA = (64 queries, 1 head), 128 threads.
// Thread (tx=tid&7, ty=tid>>3) owns a 4-query x 8-col tile of both S and O.
// K tile buffer is reused for P (scores) between the two GEMMs.
// Online softmax with per-row m/l kept (replicated) in registers; the 8
// threads sharing a row agree via 8-lane shuffle reductions.
// ---------------------------------------------------------------------------
__global__ __launch_bounds__(128)
void attn_kernel(const float* __restrict__ Q, const float* __restrict__ K,
                 const float* __restrict__ V, float* __restrict__ O)
{
    extern __shared__ float sm[];
    float* Qts = sm;                       // [64 d][64 q]  (transposed, no pad)
    float* KPs = sm + 64 * 64;             // [64][65]  K rows, later P rows
    float* Vs  = sm + 64 * 64 + 64 * 65;   // [64][64]

    const int qb  = gridDim.x - 1 - blockIdx.x;  // heavy (large qb) blocks first
    const int h   = blockIdx.y;
    const int tid = threadIdx.x;
    const int tx  = tid & 7;
    const int ty  = tid >> 3;
    const int q0  = ty * 4;
    const int c0  = tx * 8;
    const float scale = 0.125f;            // 1/sqrt(64)

    // Load Q block transposed into Qts[d][q], folding in the softmax scale.
    const float* Qg = Q + (size_t)(qb * 64) * C_DIM + h * DHEAD;
#pragma unroll
    for (int i = 0; i < 8; i++) {
        int f = tid + i * 128;
        int r = f >> 4;               // query row 0..63
        int c = (f & 15) << 2;        // d offset
        float4 v4 = *(const float4*)(Qg + (size_t)r * C_DIM + c);
        Qts[(c + 0) * 64 + r] = v4.x * scale;
        Qts[(c + 1) * 64 + r] = v4.y * scale;
        Qts[(c + 2) * 64 + r] = v4.z * scale;
        Qts[(c + 3) * 64 + r] = v4.w * scale;
    }

    float o[4][8];
    float m[4], l[4];
#pragma unroll
    for (int i = 0; i < 4; i++) {
        m[i] = -1e30f; l[i] = 0.f;
#pragma unroll
        for (int j = 0; j < 8; j++) o[i][j] = 0.f;
    }

    for (int kb = 0; kb <= qb; kb++) {
        __syncthreads();   // previous P/V consumed (and Q load done on iter 0)

        const float* Kg = K + (size_t)(kb * 64) * C_DIM + h * DHEAD;
        const float* Vg = V + (size_t)(kb * 64) * C_DIM + h * DHEAD;
#pragma unroll
        for (int i = 0; i < 8; i++) {
            int f = tid + i * 128;
            int r = f >> 4;
            int c = (f & 15) << 2;
            float4 k4 = *(const float4*)(Kg + (size_t)r * C_DIM + c);
            KPs[r * 65 + c + 0] = k4.x; KPs[r * 65 + c + 1] = k4.y;
            KPs[r * 65 + c + 2] = k4.z; KPs[r * 65 + c + 3] = k4.w;
            float4 vv = *(const float4*)(Vg + (size_t)r * C_DIM + c);
            *(float4*)&Vs[r * 64 + c] = vv;
        }
        __syncthreads();

        // ---- S = (Q*scale) @ K^T ------------------------------------------
        float s[4][8];
#pragma unroll
        for (int i = 0; i < 4; i++)
#pragma unroll
            for (int j = 0; j < 8; j++) s[i][j] = 0.f;

#pragma unroll 4
        for (int d = 0; d < 64; d++) {
            float4 aq = *(const float4*)&Qts[d * 64 + q0];
            float a0 = aq.x, a1 = aq.y, a2 = aq.z, a3 = aq.w;
#pragma unroll
            for (int j = 0; j < 8; j++) {
                float bk = KPs[(c0 + j) * 65 + d];
                s[0][j] += a0 * bk;
                s[1][j] += a1 * bk;
                s[2][j] += a2 * bk;
                s[3][j] += a3 * bk;
            }
        }

        if (kb == qb) {   // causal mask on the diagonal block
#pragma unroll
            for (int i = 0; i < 4; i++)
#pragma unroll
                for (int j = 0; j < 8; j++)
                    if (c0 + j > q0 + i) s[i][j] = -1e30f;
        }

        // ---- online softmax update ----------------------------------------
#pragma unroll
        for (int i = 0; i < 4; i++) {
            float mx = s[i][0];
#pragma unroll
            for (int j = 1; j < 8; j++) mx = fmaxf(mx, s[i][j]);
            mx = fmaxf(mx, __shfl_xor_sync(0xffffffffu, mx, 1, 8));
            mx = fmaxf(mx, __shfl_xor_sync(0xffffffffu, mx, 2, 8));
            mx = fmaxf(mx, __shfl_xor_sync(0xffffffffu, mx, 4, 8));
            float mnew = fmaxf(m[i], mx);
            float corr = __expf(m[i] - mnew);
            m[i] = mnew;
            float ssum = 0.f;
#pragma unroll
            for (int j = 0; j < 8; j++) {
                float p = __expf(s[i][j] - mnew);
                s[i][j] = p;
                ssum += p;
            }
            ssum += __shfl_xor_sync(0xffffffffu, ssum, 1, 8);
            ssum += __shfl_xor_sync(0xffffffffu, ssum, 2, 8);
            ssum += __shfl_xor_sync(0xffffffffu, ssum, 4, 8);
            l[i] = l[i] * corr + ssum;
#pragma unroll
            for (int j = 0; j < 8; j++) o[i][j] *= corr;
        }

        __syncthreads();   // all warps done reading K from KPs
#pragma unroll
        for (int i = 0; i < 4; i++)
#pragma unroll
            for (int j = 0; j < 8; j++)
                KPs[(q0 + i) * 65 + c0 + j] = s[i][j];
        __syncthreads();   // P ready

        // ---- O += P @ V ----------------------------------------------------
#pragma unroll 4
        for (int ss = 0; ss < 64; ss++) {
            float p0 = KPs[(q0 + 0) * 65 + ss];
            float p1 = KPs[(q0 + 1) * 65 + ss];
            float p2 = KPs[(q0 + 2) * 65 + ss];
            float p3 = KPs[(q0 + 3) * 65 + ss];
            float4 v0 = *(const float4*)&Vs[ss * 64 + c0];
            float4 v1 = *(const float4*)&Vs[ss * 64 + c0 + 4];
            float b[8] = {v0.x, v0.y, v0.z, v0.w, v1.x, v1.y, v1.z, v1.w};
#pragma unroll
            for (int j = 0; j < 8; j++) {
                o[0][j] += p0 * b[j];
                o[1][j] += p1 * b[j];
                o[2][j] += p2 * b[j];
                o[3][j] += p3 * b[j];
            }
        }
    }

    // ---- epilogue: O /= l, write (T, H, D) layout -------------------------
    float* Og = O + (size_t)(qb * 64) * C_DIM + h * DHEAD;
#pragma unroll
    for (int i = 0; i < 4; i++) {
        float inv = 1.f / l[i];
        float4 w0, w1;
        w0.x = o[i][0] * inv; w0.y = o[i][1] * inv;
        w0.z = o[i][2] * inv; w0.w = o[i][3] * inv;
        w1.x = o[i][4] * inv; w1.y = o[i][5] * inv;
        w1.z = o[i][6] * inv; w1.w = o[i][7] * inv;
        *(float4*)(Og + (size_t)(q0 + i) * C_DIM + c0)     = w0;
        *(float4*)(Og + (size_t)(q0 + i) * C_DIM + c0 + 4) = w1;
    }
}

// ---------------------------------------------------------------------------
extern "C" void kernel_launch(void* const* d_in, const int* in_sizes, int n_in,
                              void* d_out, int out_size)
{
    const float* x  = (const float*)d_in[0];
    const float* Wq = (const float*)d_in[1];
    const float* bq = (const float*)d_in[2];
    const float* Wk = (const float*)d_in[3];
    const float* bk = (const float*)d_in[4];
    const float* Wv = (const float*)d_in[5];
    const float* bv = (const float*)d_in[6];
    const float* Wp = (const float*)d_in[7];
    const float* bp = (const float*)d_in[8];
    float* out = (float*)d_out;

    float *q, *k, *v, *y;
    cudaGetSymbolAddress((void**)&q, g_q);
    cudaGetSymbolAddress((void**)&k, g_k);
    cudaGetSymbolAddress((void**)&v, g_v);
    cudaGetSymbolAddress((void**)&y, g_y);

    const int ATTN_SMEM = (64 * 64 + 64 * 65 + 64 * 64) * (int)sizeof(float);  // 49408
    cudaFuncSetAttribute(attn_kernel, cudaFuncAttributeMaxDynamicSharedMemorySize,
                         ATTN_SMEM);

    dim3 ggrid(C_DIM / 128, T_SEQ / 128);   // (8, 32)
    gemm_nt_bias<<<ggrid, 256>>>(x, Wq, bq, q, T_SEQ, C_DIM, C_DIM);
    gemm_nt_bias<<<ggrid, 256>>>(x, Wk, bk, k, T_SEQ, C_DIM, C_DIM);
    gemm_nt_bias<<<ggrid, 256>>>(x, Wv, bv, v, T_SEQ, C_DIM, C_DIM);
    attn_kernel<<<dim3(T_SEQ / 64, NHEAD), 128, ATTN_SMEM>>>(q, k, v, y);
    gemm_nt_bias<<<ggrid, 256>>>(y, Wp, bp, out, T_SEQ, C_DIM, C_DIM);
}

// round 3
// speedup vs baseline: 1.1882x; 1.1882x over previous
#include <cuda_runtime.h>
#include <cuda_bf16.h>
#include <cstdint>

#define T_SEQ 4096
#define C_DIM 1024
#define QKV_DIM 3072
#define NHEAD 16
#define DHEAD 64

// ---------------------------------------------------------------------------
// Static device scratch (no allocations allowed)
// ---------------------------------------------------------------------------
__device__ __nv_bfloat16 g_xh[T_SEQ * C_DIM];
__device__ __nv_bfloat16 g_xl[T_SEQ * C_DIM];
__device__ __nv_bfloat16 g_Wh[QKV_DIM * C_DIM];   // [Wq;Wk;Wv] hi
__device__ __nv_bfloat16 g_Wl[QKV_DIM * C_DIM];   // [Wq;Wk;Wv] lo
__device__ __nv_bfloat16 g_Wph[C_DIM * C_DIM];
__device__ __nv_bfloat16 g_Wpl[C_DIM * C_DIM];
__device__ float         g_bqkv[QKV_DIM];
__device__ float         g_qkv[T_SEQ * QKV_DIM];  // fused q|k|v, row stride 3072
__device__ float         g_y[T_SEQ * C_DIM];
__device__ __nv_bfloat16 g_yh[T_SEQ * C_DIM];
__device__ __nv_bfloat16 g_yl[T_SEQ * C_DIM];

// ---------------------------------------------------------------------------
// PTX helpers (arch-agnostic: ldmatrix / mma.sync / cp.async — compile on
// compute_103; NO tcgen05, which this harness's PTX target rejects)
// ---------------------------------------------------------------------------
__device__ __forceinline__ uint32_t smem_u32(const void* p) {
    uint32_t a;
    asm("{ .reg .u64 t; cvta.to.shared.u64 t, %1; cvt.u32.u64 %0, t; }"
        : "=r"(a) : "l"(p));
    return a;
}

__device__ __forceinline__ void cp16(uint32_t dst, const void* src) {
    asm volatile("cp.async.cg.shared.global [%0], [%1], 16;" :: "r"(dst), "l"(src));
}
__device__ __forceinline__ void cp_commit() {
    asm volatile("cp.async.commit_group;" ::: "memory");
}
__device__ __forceinline__ void cp_wait0() {
    asm volatile("cp.async.wait_group 0;" ::: "memory");
}
__device__ __forceinline__ void cp_wait1() {
    asm volatile("cp.async.wait_group 1;" ::: "memory");
}

__device__ __forceinline__ void ldsm4(uint32_t* r, uint32_t addr) {
    asm volatile("ldmatrix.sync.aligned.m8n8.x4.shared.b16 {%0,%1,%2,%3}, [%4];"
                 : "=r"(r[0]), "=r"(r[1]), "=r"(r[2]), "=r"(r[3]) : "r"(addr));
}
__device__ __forceinline__ void ldsm2(uint32_t* r, uint32_t addr) {
    asm volatile("ldmatrix.sync.aligned.m8n8.x2.shared.b16 {%0,%1}, [%2];"
                 : "=r"(r[0]), "=r"(r[1]) : "r"(addr));
}

__device__ __forceinline__ void mma16816(float* c, const uint32_t* a, const uint32_t* b) {
    asm volatile(
        "mma.sync.aligned.m16n8k16.row.col.f32.bf16.bf16.f32 "
        "{%0,%1,%2,%3}, {%4,%5,%6,%7}, {%8,%9}, {%0,%1,%2,%3};"
        : "+f"(c[0]), "+f"(c[1]), "+f"(c[2]), "+f"(c[3])
        : "r"(a[0]), "r"(a[1]), "r"(a[2]), "r"(a[3]), "r"(b[0]), "r"(b[1]));
}

#define SW128(o) ((o) ^ (((o) >> 3) & 0x70))

// ---------------------------------------------------------------------------
// Elementwise: split fp32 -> bf16 hi + bf16 lo
// ---------------------------------------------------------------------------
__global__ void split_kernel(const float4* __restrict__ src,
                             __nv_bfloat162* __restrict__ h,
                             __nv_bfloat162* __restrict__ l, int n4)
{
    int i = blockIdx.x * blockDim.x + threadIdx.x;
    if (i >= n4) return;
    float4 v = src[i];
    __nv_bfloat16 h0 = __float2bfloat16(v.x);
    __nv_bfloat16 h1 = __float2bfloat16(v.y);
    __nv_bfloat16 h2 = __float2bfloat16(v.z);
    __nv_bfloat16 h3 = __float2bfloat16(v.w);
    __nv_bfloat16 l0 = __float2bfloat16(v.x - __bfloat162float(h0));
    __nv_bfloat16 l1 = __float2bfloat16(v.y - __bfloat162float(h1));
    __nv_bfloat16 l2 = __float2bfloat16(v.z - __bfloat162float(h2));
    __nv_bfloat16 l3 = __float2bfloat16(v.w - __bfloat162float(h3));
    h[i * 2]     = __halves2bfloat162(h0, h1);
    h[i * 2 + 1] = __halves2bfloat162(h2, h3);
    l[i * 2]     = __halves2bfloat162(l0, l1);
    l[i * 2 + 1] = __halves2bfloat162(l2, l3);
}

__global__ void concat_bias(const float* __restrict__ bq, const float* __restrict__ bk,
                            const float* __restrict__ bv, float* __restrict__ dst)
{
    int i = blockIdx.x * blockDim.x + threadIdx.x;
    if (i < 1024)      dst[i] = bq[i];
    else if (i < 2048) dst[i] = bk[i - 1024];
    else               dst[i] = bv[i - 2048];
}

// ---------------------------------------------------------------------------
// mma.sync split-bf16 GEMM (NT): C[M,N] = (Ah+Al)[M,K] @ (Bh+Bl)[N,K]^T + bias
// 128x128 tile, BK=64, 256 threads (8 warps, 2x4; 64x32 per warp).
// SMEM: per stage {Ah,Al,Bh,Bl} each 128 rows x 128B, SW128 swizzled = 64KB;
// double-buffered via cp.async = 128KB.
// ---------------------------------------------------------------------------
#define GEMM_SMEM (2 * 4 * 16384)

__global__ __launch_bounds__(256, 1)
void gemm_bf16s(const __nv_bfloat16* __restrict__ Ah, const __nv_bfloat16* __restrict__ Al,
                const __nv_bfloat16* __restrict__ Bh, const __nv_bfloat16* __restrict__ Bl,
                const float* __restrict__ bias, float* __restrict__ C,
                int N, int K)
{
    extern __shared__ char smem[];
    const int tid  = threadIdx.x;
    const int warp = tid >> 5;
    const int lane = tid & 31;
    const int wm   = warp >> 2;          // 0..1 -> m offset 64*wm
    const int wn   = warp & 3;           // 0..3 -> n offset 32*wn
    const int m0   = blockIdx.y * 128;
    const int n0   = blockIdx.x * 128;
    const uint32_t sbase = smem_u32(smem);
    const int NC = K / 64;

    // ---- async loader: thread -> row tid/2, chunks (tid&1)*4 .. +3 ----
    const int lrow = tid >> 1;
    const int lj0  = (tid & 1) * 4;

    auto load_stage = [&](int c, int s) {
        const uint32_t sb = sbase + s * 65536;
        const size_t ka = (size_t)(m0 + lrow) * K + c * 64;
        const size_t kb = (size_t)(n0 + lrow) * K + c * 64;
#pragma unroll
        for (int j = lj0; j < lj0 + 4; j++) {
            uint32_t sw = SW128(lrow * 128 + j * 16);
            cp16(sb + sw,         Ah + ka + j * 8);
            cp16(sb + 16384 + sw, Al + ka + j * 8);
            cp16(sb + 32768 + sw, Bh + kb + j * 8);
            cp16(sb + 49152 + sw, Bl + kb + j * 8);
        }
        cp_commit();
    };

    float acc[4][4][4];
#pragma unroll
    for (int i = 0; i < 4; i++)
#pragma unroll
        for (int j = 0; j < 4; j++)
#pragma unroll
            for (int q = 0; q < 4; q++) acc[i][j][q] = 0.f;

    // ldmatrix lane address components
    const int alr = lane & 15;            // A row-lane (0..15)
    const int alk = (lane >> 4) & 1;      // A k-half (16B)
    const int bl_ = lane & 15;
    const int bro = bl_ & 7;              // B row-lane (0..7)
    const int bk_ = (bl_ >> 3) & 1;       // B k-half

    load_stage(0, 0);

    for (int c = 0; c < NC; c++) {
        const int s = c & 1;
        if (c + 1 < NC) { load_stage(c + 1, s ^ 1); cp_wait1(); }
        else            { cp_wait0(); }
        __syncthreads();

        const uint32_t sb  = sbase + s * 65536;
#pragma unroll
        for (int kk = 0; kk < 4; kk++) {
            uint32_t ah[4][4], al4[4][4], bh[4][2], bl4[4][2];
#pragma unroll
            for (int mi = 0; mi < 4; mi++) {
                uint32_t off = SW128((wm * 64 + mi * 16 + alr) * 128 + kk * 32 + alk * 16);
                ldsm4(ah[mi],  sb + off);
                ldsm4(al4[mi], sb + 16384 + off);
            }
#pragma unroll
            for (int ni = 0; ni < 4; ni++) {
                uint32_t off = SW128((wn * 32 + ni * 8 + bro) * 128 + kk * 32 + bk_ * 16);
                ldsm2(bh[ni],  sb + 32768 + off);
                ldsm2(bl4[ni], sb + 49152 + off);
            }
#pragma unroll
            for (int mi = 0; mi < 4; mi++)
#pragma unroll
                for (int ni = 0; ni < 4; ni++) {
                    mma16816(acc[mi][ni], ah[mi],  bh[ni]);
                    mma16816(acc[mi][ni], ah[mi],  bl4[ni]);
                    mma16816(acc[mi][ni], al4[mi], bh[ni]);
                }
        }
        __syncthreads();
    }

    // ---- epilogue ----
    const int g   = lane >> 2;
    const int tig = lane & 3;
#pragma unroll
    for (int mi = 0; mi < 4; mi++) {
#pragma unroll
        for (int ni = 0; ni < 4; ni++) {
            int row = m0 + wm * 64 + mi * 16 + g;
            int col = n0 + wn * 32 + ni * 8 + tig * 2;
            float b0 = bias[col], b1 = bias[col + 1];
            float2 v0 = {acc[mi][ni][0] + b0, acc[mi][ni][1] + b1};
            float2 v1 = {acc[mi][ni][2] + b0, acc[mi][ni][3] + b1};
            *(float2*)(C + (size_t)row * N + col)       = v0;
            *(float2*)(C + (size_t)(row + 8) * N + col) = v1;
        }
    }
}

// ---------------------------------------------------------------------------
// Flash attention, fp32 (unchanged from R1 pass; reads fused qkv, stride 3072)
// ---------------------------------------------------------------------------
__global__ __launch_bounds__(128)
void attn_kernel(const float* __restrict__ QKV, float* __restrict__ O)
{
    extern __shared__ float sm[];
    float* Qts = sm;                       // [64 d][64 q]
    float* KPs = sm + 64 * 64;             // [64][65]
    float* Vs  = sm + 64 * 64 + 64 * 65;   // [64][64]

    const int qb  = gridDim.x - 1 - blockIdx.x;
    const int h   = blockIdx.y;
    const int tid = threadIdx.x;
    const int tx  = tid & 7;
    const int ty  = tid >> 3;
    const int q0  = ty * 4;
    const int c0  = tx * 8;
    const float scale = 0.125f;

    const float* Qg = QKV + (size_t)(qb * 64) * QKV_DIM + h * DHEAD;
#pragma unroll
    for (int i = 0; i < 8; i++) {
        int f = tid + i * 128;
        int r = f >> 4;
        int c = (f & 15) << 2;
        float4 v4 = *(const float4*)(Qg + (size_t)r * QKV_DIM + c);
        Qts[(c + 0) * 64 + r] = v4.x * scale;
        Qts[(c + 1) * 64 + r] = v4.y * scale;
        Qts[(c + 2) * 64 + r] = v4.z * scale;
        Qts[(c + 3) * 64 + r] = v4.w * scale;
    }

    float o[4][8];
    float m[4], l[4];
#pragma unroll
    for (int i = 0; i < 4; i++) {
        m[i] = -1e30f; l[i] = 0.f;
#pragma unroll
        for (int j = 0; j < 8; j++) o[i][j] = 0.f;
    }

    for (int kb = 0; kb <= qb; kb++) {
        __syncthreads();

        const float* Kg = QKV + (size_t)(kb * 64) * QKV_DIM + C_DIM + h * DHEAD;
        const float* Vg = QKV + (size_t)(kb * 64) * QKV_DIM + 2 * C_DIM + h * DHEAD;
#pragma unroll
        for (int i = 0; i < 8; i++) {
            int f = tid + i * 128;
            int r = f >> 4;
            int c = (f & 15) << 2;
            float4 k4 = *(const float4*)(Kg + (size_t)r * QKV_DIM + c);
            KPs[r * 65 + c + 0] = k4.x; KPs[r * 65 + c + 1] = k4.y;
            KPs[r * 65 + c + 2] = k4.z; KPs[r * 65 + c + 3] = k4.w;
            float4 vv = *(const float4*)(Vg + (size_t)r * QKV_DIM + c);
            *(float4*)&Vs[r * 64 + c] = vv;
        }
        __syncthreads();

        float s[4][8];
#pragma unroll
        for (int i = 0; i < 4; i++)
#pragma unroll
            for (int j = 0; j < 8; j++) s[i][j] = 0.f;

#pragma unroll 4
        for (int d = 0; d < 64; d++) {
            float4 aq = *(const float4*)&Qts[d * 64 + q0];
            float a0 = aq.x, a1 = aq.y, a2 = aq.z, a3 = aq.w;
#pragma unroll
            for (int j = 0; j < 8; j++) {
                float bk = KPs[(c0 + j) * 65 + d];
                s[0][j] += a0 * bk;
                s[1][j] += a1 * bk;
                s[2][j] += a2 * bk;
                s[3][j] += a3 * bk;
            }
        }

        if (kb == qb) {
#pragma unroll
            for (int i = 0; i < 4; i++)
#pragma unroll
                for (int j = 0; j < 8; j++)
                    if (c0 + j > q0 + i) s[i][j] = -1e30f;
        }

#pragma unroll
        for (int i = 0; i < 4; i++) {
            float mx = s[i][0];
#pragma unroll
            for (int j = 1; j < 8; j++) mx = fmaxf(mx, s[i][j]);
            mx = fmaxf(mx, __shfl_xor_sync(0xffffffffu, mx, 1, 8));
            mx = fmaxf(mx, __shfl_xor_sync(0xffffffffu, mx, 2, 8));
            mx = fmaxf(mx, __shfl_xor_sync(0xffffffffu, mx, 4, 8));
            float mnew = fmaxf(m[i], mx);
            float corr = __expf(m[i] - mnew);
            m[i] = mnew;
            float ssum = 0.f;
#pragma unroll
            for (int j = 0; j < 8; j++) {
                float p = __expf(s[i][j] - mnew);
                s[i][j] = p;
                ssum += p;
            }
            ssum += __shfl_xor_sync(0xffffffffu, ssum, 1, 8);
            ssum += __shfl_xor_sync(0xffffffffu, ssum, 2, 8);
            ssum += __shfl_xor_sync(0xffffffffu, ssum, 4, 8);
            l[i] = l[i] * corr + ssum;
#pragma unroll
            for (int j = 0; j < 8; j++) o[i][j] *= corr;
        }

        __syncthreads();
#pragma unroll
        for (int i = 0; i < 4; i++)
#pragma unroll
            for (int j = 0; j < 8; j++)
                KPs[(q0 + i) * 65 + c0 + j] = s[i][j];
        __syncthreads();

#pragma unroll 4
        for (int ss = 0; ss < 64; ss++) {
            float p0 = KPs[(q0 + 0) * 65 + ss];
            float p1 = KPs[(q0 + 1) * 65 + ss];
            float p2 = KPs[(q0 + 2) * 65 + ss];
            float p3 = KPs[(q0 + 3) * 65 + ss];
            float4 v0 = *(const float4*)&Vs[ss * 64 + c0];
            float4 v1 = *(const float4*)&Vs[ss * 64 + c0 + 4];
            float b[8] = {v0.x, v0.y, v0.z, v0.w, v1.x, v1.y, v1.z, v1.w};
#pragma unroll
            for (int j = 0; j < 8; j++) {
                o[0][j] += p0 * b[j];
                o[1][j] += p1 * b[j];
                o[2][j] += p2 * b[j];
                o[3][j] += p3 * b[j];
            }
        }
    }

    float* Og = O + (size_t)(qb * 64) * C_DIM + h * DHEAD;
#pragma unroll
    for (int i = 0; i < 4; i++) {
        float inv = 1.f / l[i];
        float4 w0, w1;
        w0.x = o[i][0] * inv; w0.y = o[i][1] * inv;
        w0.z = o[i][2] * inv; w0.w = o[i][3] * inv;
        w1.x = o[i][4] * inv; w1.y = o[i][5] * inv;
        w1.z = o[i][6] * inv; w1.w = o[i][7] * inv;
        *(float4*)(Og + (size_t)(q0 + i) * C_DIM + c0)     = w0;
        *(float4*)(Og + (size_t)(q0 + i) * C_DIM + c0 + 4) = w1;
    }
}

// ---------------------------------------------------------------------------
extern "C" void kernel_launch(void* const* d_in, const int* in_sizes, int n_in,
                              void* d_out, int out_size)
{
    const float* x  = (const float*)d_in[0];
    const float* Wq = (const float*)d_in[1];
    const float* bq = (const float*)d_in[2];
    const float* Wk = (const float*)d_in[3];
    const float* bk = (const float*)d_in[4];
    const float* Wv = (const float*)d_in[5];
    const float* bv = (const float*)d_in[6];
    const float* Wp = (const float*)d_in[7];
    const float* bp = (const float*)d_in[8];
    float* out = (float*)d_out;

    __nv_bfloat16 *xh, *xl, *Wh, *Wl, *Wph, *Wpl, *yh, *yl;
    float *qkv, *y, *bqkv;
    cudaGetSymbolAddress((void**)&xh,   g_xh);
    cudaGetSymbolAddress((void**)&xl,   g_xl);
    cudaGetSymbolAddress((void**)&Wh,   g_Wh);
    cudaGetSymbolAddress((void**)&Wl,   g_Wl);
    cudaGetSymbolAddress((void**)&Wph,  g_Wph);
    cudaGetSymbolAddress((void**)&Wpl,  g_Wpl);
    cudaGetSymbolAddress((void**)&yh,   g_yh);
    cudaGetSymbolAddress((void**)&yl,   g_yl);
    cudaGetSymbolAddress((void**)&qkv,  g_qkv);
    cudaGetSymbolAddress((void**)&y,    g_y);
    cudaGetSymbolAddress((void**)&bqkv, g_bqkv);

    cudaFuncSetAttribute(gemm_bf16s, cudaFuncAttributeMaxDynamicSharedMemorySize,
                         GEMM_SMEM);
    const int ATTN_SMEM = (64 * 64 + 64 * 65 + 64 * 64) * (int)sizeof(float);
    cudaFuncSetAttribute(attn_kernel, cudaFuncAttributeMaxDynamicSharedMemorySize,
                         ATTN_SMEM);

    // split inputs/weights into bf16 hi+lo
    split_kernel<<<4096, 256>>>((const float4*)x,  (__nv_bfloat162*)xh,  (__nv_bfloat162*)xl,  1048576);
    split_kernel<<<1024, 256>>>((const float4*)Wq, (__nv_bfloat162*)Wh,  (__nv_bfloat162*)Wl,  262144);
    split_kernel<<<1024, 256>>>((const float4*)Wk, (__nv_bfloat162*)(Wh + 1024 * 1024),
                                (__nv_bfloat162*)(Wl + 1024 * 1024), 262144);
    split_kernel<<<1024, 256>>>((const float4*)Wv, (__nv_bfloat162*)(Wh + 2 * 1024 * 1024),
                                (__nv_bfloat162*)(Wl + 2 * 1024 * 1024), 262144);
    split_kernel<<<1024, 256>>>((const float4*)Wp, (__nv_bfloat162*)Wph, (__nv_bfloat162*)Wpl, 262144);
    concat_bias<<<3, 1024>>>(bq, bk, bv, bqkv);

    // fused QKV projection: [4096,1024] @ [3072,1024]^T -> [4096,3072]
    gemm_bf16s<<<dim3(QKV_DIM / 128, T_SEQ / 128), 256, GEMM_SMEM>>>(
        xh, xl, Wh, Wl, bqkv, qkv, QKV_DIM, C_DIM);

    attn_kernel<<<dim3(T_SEQ / 64, NHEAD), 128, ATTN_SMEM>>>(qkv, y);

    split_kernel<<<4096, 256>>>((const float4*)y, (__nv_bfloat162*)yh, (__nv_bfloat162*)yl, 1048576);

    // output projection: [4096,1024] @ [1024,1024]^T -> [4096,1024]
    gemm_bf16s<<<dim3(C_DIM / 128, T_SEQ / 128), 256, GEMM_SMEM>>>(
        yh, yl, Wph, Wpl, bp, out, C_DIM, C_DIM);
}

// round 4
// speedup vs baseline: 2.9431x; 2.4769x over previous
#include <cuda_runtime.h>
#include <cuda_bf16.h>
#include <cstdint>

#define T_SEQ 4096
#define C_DIM 1024
#define QKV_DIM 3072
#define NHEAD 16
#define DHEAD 64

// ---------------------------------------------------------------------------
// Static device scratch (no allocations allowed)
// ---------------------------------------------------------------------------
__device__ __nv_bfloat16 g_xh[T_SEQ * C_DIM];
__device__ __nv_bfloat16 g_xl[T_SEQ * C_DIM];
__device__ __nv_bfloat16 g_Wh[QKV_DIM * C_DIM];   // [Wq;Wk;Wv] hi
__device__ __nv_bfloat16 g_Wl[QKV_DIM * C_DIM];   // [Wq;Wk;Wv] lo
__device__ __nv_bfloat16 g_Wph[C_DIM * C_DIM];
__device__ __nv_bfloat16 g_Wpl[C_DIM * C_DIM];
__device__ float         g_bqkv[QKV_DIM];
__device__ __nv_bfloat16 g_qkvh[T_SEQ * QKV_DIM]; // fused q|k|v hi (q pre-scaled)
__device__ __nv_bfloat16 g_qkvl[T_SEQ * QKV_DIM]; // fused q|k|v lo
__device__ __nv_bfloat16 g_yh[T_SEQ * C_DIM];
__device__ __nv_bfloat16 g_yl[T_SEQ * C_DIM];

// ---------------------------------------------------------------------------
// PTX helpers (arch-agnostic; no tcgen05 — harness PTX target rejects it)
// ---------------------------------------------------------------------------
__device__ __forceinline__ uint32_t smem_u32(const void* p) {
    uint32_t a;
    asm("{ .reg .u64 t; cvta.to.shared.u64 t, %1; cvt.u32.u64 %0, t; }"
        : "=r"(a) : "l"(p));
    return a;
}
__device__ __forceinline__ void cp16(uint32_t dst, const void* src) {
    asm volatile("cp.async.cg.shared.global [%0], [%1], 16;" :: "r"(dst), "l"(src));
}
__device__ __forceinline__ void cp_commit() {
    asm volatile("cp.async.commit_group;" ::: "memory");
}
__device__ __forceinline__ void cp_wait0() {
    asm volatile("cp.async.wait_group 0;" ::: "memory");
}
__device__ __forceinline__ void cp_wait1() {
    asm volatile("cp.async.wait_group 1;" ::: "memory");
}
__device__ __forceinline__ void ldsm4(uint32_t* r, uint32_t addr) {
    asm volatile("ldmatrix.sync.aligned.m8n8.x4.shared.b16 {%0,%1,%2,%3}, [%4];"
                 : "=r"(r[0]), "=r"(r[1]), "=r"(r[2]), "=r"(r[3]) : "r"(addr));
}
__device__ __forceinline__ void ldsm2(uint32_t* r, uint32_t addr) {
    asm volatile("ldmatrix.sync.aligned.m8n8.x2.shared.b16 {%0,%1}, [%2];"
                 : "=r"(r[0]), "=r"(r[1]) : "r"(addr));
}
__device__ __forceinline__ void ldsm2t(uint32_t* r, uint32_t addr) {
    asm volatile("ldmatrix.sync.aligned.m8n8.x2.trans.shared.b16 {%0,%1}, [%2];"
                 : "=r"(r[0]), "=r"(r[1]) : "r"(addr));
}
__device__ __forceinline__ void mma16816(float* c, const uint32_t* a, const uint32_t* b) {
    asm volatile(
        "mma.sync.aligned.m16n8k16.row.col.f32.bf16.bf16.f32 "
        "{%0,%1,%2,%3}, {%4,%5,%6,%7}, {%8,%9}, {%0,%1,%2,%3};"
        : "+f"(c[0]), "+f"(c[1]), "+f"(c[2]), "+f"(c[3])
        : "r"(a[0]), "r"(a[1]), "r"(a[2]), "r"(a[3]), "r"(b[0]), "r"(b[1]));
}
__device__ __forceinline__ uint32_t packbf(float a, float b) {
    __nv_bfloat162 t = __floats2bfloat162_rn(a, b);
    return *(uint32_t*)&t;
}

#define SW128(o) ((o) ^ (((o) >> 3) & 0x70))

// ---------------------------------------------------------------------------
// Elementwise: split fp32 -> bf16 hi + bf16 lo
// ---------------------------------------------------------------------------
__global__ void split_kernel(const float4* __restrict__ src,
                             __nv_bfloat162* __restrict__ h,
                             __nv_bfloat162* __restrict__ l, int n4)
{
    int i = blockIdx.x * blockDim.x + threadIdx.x;
    if (i >= n4) return;
    float4 v = src[i];
    __nv_bfloat16 h0 = __float2bfloat16(v.x);
    __nv_bfloat16 h1 = __float2bfloat16(v.y);
    __nv_bfloat16 h2 = __float2bfloat16(v.z);
    __nv_bfloat16 h3 = __float2bfloat16(v.w);
    __nv_bfloat16 l0 = __float2bfloat16(v.x - __bfloat162float(h0));
    __nv_bfloat16 l1 = __float2bfloat16(v.y - __bfloat162float(h1));
    __nv_bfloat16 l2 = __float2bfloat16(v.z - __bfloat162float(h2));
    __nv_bfloat16 l3 = __float2bfloat16(v.w - __bfloat162float(h3));
    h[i * 2]     = __halves2bfloat162(h0, h1);
    h[i * 2 + 1] = __halves2bfloat162(h2, h3);
    l[i * 2]     = __halves2bfloat162(l0, l1);
    l[i * 2 + 1] = __halves2bfloat162(l2, l3);
}

__global__ void concat_bias(const float* __restrict__ bq, const float* __restrict__ bk,
                            const float* __restrict__ bv, float* __restrict__ dst)
{
    int i = blockIdx.x * blockDim.x + threadIdx.x;
    if (i < 1024)      dst[i] = bq[i];
    else if (i < 2048) dst[i] = bk[i - 1024];
    else               dst[i] = bv[i - 2048];
}

// ---------------------------------------------------------------------------
// mma.sync split-bf16 GEMM (NT): C = (Ah+Al) @ (Bh+Bl)^T + bias
// mode 0: fp32 C.  mode 1: split-bf16 Ch/Cl, with 0.125 scale on cols < C_DIM.
// ---------------------------------------------------------------------------
#define GEMM_SMEM (2 * 4 * 16384)

__global__ __launch_bounds__(256, 1)
void gemm_bf16s(const __nv_bfloat16* __restrict__ Ah, const __nv_bfloat16* __restrict__ Al,
                const __nv_bfloat16* __restrict__ Bh, const __nv_bfloat16* __restrict__ Bl,
                const float* __restrict__ bias, float* __restrict__ C,
                __nv_bfloat16* __restrict__ Ch, __nv_bfloat16* __restrict__ Cl,
                int N, int K, int mode)
{
    extern __shared__ char smem[];
    const int tid  = threadIdx.x;
    const int warp = tid >> 5;
    const int lane = tid & 31;
    const int wm   = warp >> 2;
    const int wn   = warp & 3;
    const int m0   = blockIdx.y * 128;
    const int n0   = blockIdx.x * 128;
    const uint32_t sbase = smem_u32(smem);
    const int NC = K / 64;

    const int lrow = tid >> 1;
    const int lj0  = (tid & 1) * 4;

    auto load_stage = [&](int c, int s) {
        const uint32_t sb = sbase + s * 65536;
        const size_t ka = (size_t)(m0 + lrow) * K + c * 64;
        const size_t kb = (size_t)(n0 + lrow) * K + c * 64;
#pragma unroll
        for (int j = lj0; j < lj0 + 4; j++) {
            uint32_t sw = SW128(lrow * 128 + j * 16);
            cp16(sb + sw,         Ah + ka + j * 8);
            cp16(sb + 16384 + sw, Al + ka + j * 8);
            cp16(sb + 32768 + sw, Bh + kb + j * 8);
            cp16(sb + 49152 + sw, Bl + kb + j * 8);
        }
        cp_commit();
    };

    float acc[4][4][4];
#pragma unroll
    for (int i = 0; i < 4; i++)
#pragma unroll
        for (int j = 0; j < 4; j++)
#pragma unroll
            for (int q = 0; q < 4; q++) acc[i][j][q] = 0.f;

    const int alr = lane & 15;
    const int alk = (lane >> 4) & 1;
    const int bro = lane & 7;
    const int bk_ = (lane >> 3) & 1;

    load_stage(0, 0);

    for (int c = 0; c < NC; c++) {
        const int s = c & 1;
        if (c + 1 < NC) { load_stage(c + 1, s ^ 1); cp_wait1(); }
        else            { cp_wait0(); }
        __syncthreads();

        const uint32_t sb = sbase + s * 65536;
#pragma unroll
        for (int kk = 0; kk < 4; kk++) {
            uint32_t ah[4][4], al4[4][4], bh[4][2], bl4[4][2];
#pragma unroll
            for (int mi = 0; mi < 4; mi++) {
                uint32_t off = SW128((wm * 64 + mi * 16 + alr) * 128 + kk * 32 + alk * 16);
                ldsm4(ah[mi],  sb + off);
                ldsm4(al4[mi], sb + 16384 + off);
            }
#pragma unroll
            for (int ni = 0; ni < 4; ni++) {
                uint32_t off = SW128((wn * 32 + ni * 8 + bro) * 128 + kk * 32 + bk_ * 16);
                ldsm2(bh[ni],  sb + 32768 + off);
                ldsm2(bl4[ni], sb + 49152 + off);
            }
#pragma unroll
            for (int mi = 0; mi < 4; mi++)
#pragma unroll
                for (int ni = 0; ni < 4; ni++) {
                    mma16816(acc[mi][ni], ah[mi],  bh[ni]);
                    mma16816(acc[mi][ni], ah[mi],  bl4[ni]);
                    mma16816(acc[mi][ni], al4[mi], bh[ni]);
                }
        }
        __syncthreads();
    }

    const int g   = lane >> 2;
    const int tig = lane & 3;
#pragma unroll
    for (int mi = 0; mi < 4; mi++) {
#pragma unroll
        for (int ni = 0; ni < 4; ni++) {
            int row = m0 + wm * 64 + mi * 16 + g;
            int col = n0 + wn * 32 + ni * 8 + tig * 2;
            float b0 = bias[col], b1 = bias[col + 1];
            if (mode == 0) {
                float2 v0 = {acc[mi][ni][0] + b0, acc[mi][ni][1] + b1};
                float2 v1 = {acc[mi][ni][2] + b0, acc[mi][ni][3] + b1};
                *(float2*)(C + (size_t)row * N + col)       = v0;
                *(float2*)(C + (size_t)(row + 8) * N + col) = v1;
            } else {
                float sc = (col < C_DIM) ? 0.125f : 1.0f;   // softmax scale on q
                float v00 = (acc[mi][ni][0] + b0) * sc;
                float v01 = (acc[mi][ni][1] + b1) * sc;
                float v10 = (acc[mi][ni][2] + b0) * sc;
                float v11 = (acc[mi][ni][3] + b1) * sc;
                __nv_bfloat162 h0 = __floats2bfloat162_rn(v00, v01);
                __nv_bfloat162 h1 = __floats2bfloat162_rn(v10, v11);
                __nv_bfloat162 l0 = __floats2bfloat162_rn(v00 - __low2float(h0),
                                                          v01 - __high2float(h0));
                __nv_bfloat162 l1 = __floats2bfloat162_rn(v10 - __low2float(h1),
                                                          v11 - __high2float(h1));
                *(__nv_bfloat162*)(Ch + (size_t)row * N + col)       = h0;
                *(__nv_bfloat162*)(Ch + (size_t)(row + 8) * N + col) = h1;
                *(__nv_bfloat162*)(Cl + (size_t)row * N + col)       = l0;
                *(__nv_bfloat162*)(Cl + (size_t)(row + 8) * N + col) = l1;
            }
        }
    }
}

// ---------------------------------------------------------------------------
// Flash attention via mma.sync, split-bf16 inputs (q pre-scaled by 0.125).
// CTA = 64 queries x 1 head, 4 warps (16 q-rows each), 128 threads.
// SMEM: qh|ql (16KB) + 2 stages of {kh,kl,vh,vl} (32KB each) = 80KB.
// S fragments -> P fragments in registers (C-frag == A-frag layout).
// ---------------------------------------------------------------------------
#define ATTN_SMEM (16384 + 2 * 32768)

__global__ __launch_bounds__(128, 2)
void attn_mma(const __nv_bfloat16* __restrict__ qkvh,
              const __nv_bfloat16* __restrict__ qkvl,
              __nv_bfloat16* __restrict__ Yh, __nv_bfloat16* __restrict__ Yl)
{
    extern __shared__ char smem[];
    const uint32_t sb = smem_u32(smem);
    const int qb   = gridDim.x - 1 - blockIdx.x;   // heavy blocks first
    const int h    = blockIdx.y;
    const int tid  = threadIdx.x;
    const int warp = tid >> 5;
    const int lane = tid & 31;
    const int g    = lane >> 2;
    const int quad = lane & 3;

    const int lr  = tid >> 1;          // loader row 0..63
    const int lj0 = (tid & 1) * 4;

    // Q (hi/lo) -> smem [0, 16384)
    {
        const size_t base = (size_t)(qb * 64 + lr) * QKV_DIM + h * DHEAD;
#pragma unroll
        for (int j = lj0; j < lj0 + 4; j++) {
            uint32_t sw = SW128(lr * 128 + j * 16);
            cp16(sb + sw,        qkvh + base + j * 8);
            cp16(sb + 8192 + sw, qkvl + base + j * 8);
        }
    }
    auto load_kv = [&](int kb, int s) {
        const uint32_t b = sb + 16384 + s * 32768;
        const size_t kbase = (size_t)(kb * 64 + lr) * QKV_DIM + C_DIM + h * DHEAD;
        const size_t vbase = kbase + C_DIM;
#pragma unroll
        for (int j = lj0; j < lj0 + 4; j++) {
            uint32_t sw = SW128(lr * 128 + j * 16);
            cp16(b + sw,         qkvh + kbase + j * 8);
            cp16(b + 8192 + sw,  qkvl + kbase + j * 8);
            cp16(b + 16384 + sw, qkvh + vbase + j * 8);
            cp16(b + 24576 + sw, qkvl + vbase + j * 8);
        }
        cp_commit();
    };
    load_kv(0, 0);   // Q copies ride in this group

    float oacc[8][4];
#pragma unroll
    for (int i = 0; i < 8; i++)
#pragma unroll
        for (int j = 0; j < 4; j++) oacc[i][j] = 0.f;
    float mr0 = -1e30f, mr1 = -1e30f, lr0 = 0.f, lr1 = 0.f;

    const int alr = lane & 15;
    const int alk = (lane >> 4) & 1;
    const int bro = lane & 7;
    const int bk_ = (lane >> 3) & 1;

    for (int kb = 0; kb <= qb; kb++) {
        const int s = kb & 1;
        if (kb < qb) { load_kv(kb + 1, s ^ 1); cp_wait1(); }
        else         { cp_wait0(); }
        __syncthreads();

        const uint32_t kvb = sb + 16384 + s * 32768;

        // ---- S = Q K^T (split, 3 products) --------------------------------
        float sacc[8][4];
#pragma unroll
        for (int i = 0; i < 8; i++)
#pragma unroll
            for (int j = 0; j < 4; j++) sacc[i][j] = 0.f;

#pragma unroll
        for (int kk = 0; kk < 4; kk++) {
            uint32_t aqh[4], aql[4];
            uint32_t offA = SW128((warp * 16 + alr) * 128 + kk * 32 + alk * 16);
            ldsm4(aqh, sb + offA);
            ldsm4(aql, sb + 8192 + offA);
#pragma unroll
            for (int ni = 0; ni < 8; ni++) {
                uint32_t bh[2], bl[2];
                uint32_t offB = SW128((ni * 8 + bro) * 128 + kk * 32 + bk_ * 16);
                ldsm2(bh, kvb + offB);
                ldsm2(bl, kvb + 8192 + offB);
                mma16816(sacc[ni], aqh, bh);
                mma16816(sacc[ni], aqh, bl);
                mma16816(sacc[ni], aql, bh);
            }
        }

        // ---- causal mask on diagonal block --------------------------------
        if (kb == qb) {
            int r0 = warp * 16 + g, r1 = r0 + 8;
#pragma unroll
            for (int ni = 0; ni < 8; ni++) {
                int c = ni * 8 + quad * 2;
                if (c     > r0) sacc[ni][0] = -1e30f;
                if (c + 1 > r0) sacc[ni][1] = -1e30f;
                if (c     > r1) sacc[ni][2] = -1e30f;
                if (c + 1 > r1) sacc[ni][3] = -1e30f;
            }
        }

        // ---- online softmax ----------------------------------------------
        float mx0 = -1e30f, mx1 = -1e30f;
#pragma unroll
        for (int ni = 0; ni < 8; ni++) {
            mx0 = fmaxf(mx0, fmaxf(sacc[ni][0], sacc[ni][1]));
            mx1 = fmaxf(mx1, fmaxf(sacc[ni][2], sacc[ni][3]));
        }
        mx0 = fmaxf(mx0, __shfl_xor_sync(0xffffffffu, mx0, 1));
        mx0 = fmaxf(mx0, __shfl_xor_sync(0xffffffffu, mx0, 2));
        mx1 = fmaxf(mx1, __shfl_xor_sync(0xffffffffu, mx1, 1));
        mx1 = fmaxf(mx1, __shfl_xor_sync(0xffffffffu, mx1, 2));
        float mn0 = fmaxf(mr0, mx0), mn1 = fmaxf(mr1, mx1);
        float c0 = __expf(mr0 - mn0), c1 = __expf(mr1 - mn1);
        mr0 = mn0; mr1 = mn1;

        float rs0 = 0.f, rs1 = 0.f;
#pragma unroll
        for (int ni = 0; ni < 8; ni++) {
            float p0 = __expf(sacc[ni][0] - mn0);
            float p1 = __expf(sacc[ni][1] - mn0);
            float p2 = __expf(sacc[ni][2] - mn1);
            float p3 = __expf(sacc[ni][3] - mn1);
            sacc[ni][0] = p0; sacc[ni][1] = p1; sacc[ni][2] = p2; sacc[ni][3] = p3;
            rs0 += p0 + p1; rs1 += p2 + p3;
        }
        rs0 += __shfl_xor_sync(0xffffffffu, rs0, 1);
        rs0 += __shfl_xor_sync(0xffffffffu, rs0, 2);
        rs1 += __shfl_xor_sync(0xffffffffu, rs1, 1);
        rs1 += __shfl_xor_sync(0xffffffffu, rs1, 2);
        lr0 = lr0 * c0 + rs0;
        lr1 = lr1 * c1 + rs1;
#pragma unroll
        for (int di = 0; di < 8; di++) {
            oacc[di][0] *= c0; oacc[di][1] *= c0;
            oacc[di][2] *= c1; oacc[di][3] *= c1;
        }

        // ---- O += P V (split P, split V, 3 products) ----------------------
#pragma unroll
        for (int ks = 0; ks < 4; ks++) {
            uint32_t aph[4], apl[4];
            float* s0 = sacc[2 * ks];
            float* s1 = sacc[2 * ks + 1];
            aph[0] = packbf(s0[0], s0[1]);
            aph[1] = packbf(s0[2], s0[3]);
            aph[2] = packbf(s1[0], s1[1]);
            aph[3] = packbf(s1[2], s1[3]);
            __nv_bfloat162 t;
            t = *(__nv_bfloat162*)&aph[0];
            apl[0] = packbf(s0[0] - __low2float(t), s0[1] - __high2float(t));
            t = *(__nv_bfloat162*)&aph[1];
            apl[1] = packbf(s0[2] - __low2float(t), s0[3] - __high2float(t));
            t = *(__nv_bfloat162*)&aph[2];
            apl[2] = packbf(s1[0] - __low2float(t), s1[1] - __high2float(t));
            t = *(__nv_bfloat162*)&aph[3];
            apl[3] = packbf(s1[2] - __low2float(t), s1[3] - __high2float(t));
#pragma unroll
            for (int di = 0; di < 8; di++) {
                uint32_t bvh[2], bvl[2];
                uint32_t offV = SW128((ks * 16 + alr) * 128 + di * 16);
                ldsm2t(bvh, kvb + 16384 + offV);
                ldsm2t(bvl, kvb + 24576 + offV);
                mma16816(oacc[di], aph, bvh);
                mma16816(oacc[di], apl, bvh);
                mma16816(oacc[di], aph, bvl);
            }
        }
        __syncthreads();   // stage s fully consumed before it is refilled
    }

    // ---- epilogue: O /= l, split into bf16 hi/lo, write y -----------------
    float inv0 = 1.f / lr0, inv1 = 1.f / lr1;
    int r0 = qb * 64 + warp * 16 + g;
    size_t b0 = (size_t)r0 * C_DIM + h * DHEAD + quad * 2;
    size_t b1 = b0 + 8 * C_DIM;
#pragma unroll
    for (int di = 0; di < 8; di++) {
        float v00 = oacc[di][0] * inv0, v01 = oacc[di][1] * inv0;
        float v10 = oacc[di][2] * inv1, v11 = oacc[di][3] * inv1;
        __nv_bfloat162 h0 = __floats2bfloat162_rn(v00, v01);
        __nv_bfloat162 h1 = __floats2bfloat162_rn(v10, v11);
        __nv_bfloat162 l0 = __floats2bfloat162_rn(v00 - __low2float(h0),
                                                  v01 - __high2float(h0));
        __nv_bfloat162 l1 = __floats2bfloat162_rn(v10 - __low2float(h1),
                                                  v11 - __high2float(h1));
        *(__nv_bfloat162*)(Yh + b0 + di * 8) = h0;
        *(__nv_bfloat162*)(Yh + b1 + di * 8) = h1;
        *(__nv_bfloat162*)(Yl + b0 + di * 8) = l0;
        *(__nv_bfloat162*)(Yl + b1 + di * 8) = l1;
    }
}

// ---------------------------------------------------------------------------
extern "C" void kernel_launch(void* const* d_in, const int* in_sizes, int n_in,
                              void* d_out, int out_size)
{
    const float* x  = (const float*)d_in[0];
    const float* Wq = (const float*)d_in[1];
    const float* bq = (const float*)d_in[2];
    const float* Wk = (const float*)d_in[3];
    const float* bk = (const float*)d_in[4];
    const float* Wv = (const float*)d_in[5];
    const float* bv = (const float*)d_in[6];
    const float* Wp = (const float*)d_in[7];
    const float* bp = (const float*)d_in[8];
    float* out = (float*)d_out;

    __nv_bfloat16 *xh, *xl, *Wh, *Wl, *Wph, *Wpl, *yh, *yl, *qkvh, *qkvl;
    float *bqkv;
    cudaGetSymbolAddress((void**)&xh,    g_xh);
    cudaGetSymbolAddress((void**)&xl,    g_xl);
    cudaGetSymbolAddress((void**)&Wh,    g_Wh);
    cudaGetSymbolAddress((void**)&Wl,    g_Wl);
    cudaGetSymbolAddress((void**)&Wph,   g_Wph);
    cudaGetSymbolAddress((void**)&Wpl,   g_Wpl);
    cudaGetSymbolAddress((void**)&yh,    g_yh);
    cudaGetSymbolAddress((void**)&yl,    g_yl);
    cudaGetSymbolAddress((void**)&qkvh,  g_qkvh);
    cudaGetSymbolAddress((void**)&qkvl,  g_qkvl);
    cudaGetSymbolAddress((void**)&bqkv,  g_bqkv);

    cudaFuncSetAttribute(gemm_bf16s, cudaFuncAttributeMaxDynamicSharedMemorySize,
                         GEMM_SMEM);
    cudaFuncSetAttribute(attn_mma, cudaFuncAttributeMaxDynamicSharedMemorySize,
                         ATTN_SMEM);

    // split inputs/weights into bf16 hi+lo
    split_kernel<<<4096, 256>>>((const float4*)x,  (__nv_bfloat162*)xh,  (__nv_bfloat162*)xl,  1048576);
    split_kernel<<<1024, 256>>>((const float4*)Wq, (__nv_bfloat162*)Wh,  (__nv_bfloat162*)Wl,  262144);
    split_kernel<<<1024, 256>>>((const float4*)Wk, (__nv_bfloat162*)(Wh + 1024 * 1024),
                                (__nv_bfloat162*)(Wl + 1024 * 1024), 262144);
    split_kernel<<<1024, 256>>>((const float4*)Wv, (__nv_bfloat162*)(Wh + 2 * 1024 * 1024),
                                (__nv_bfloat162*)(Wl + 2 * 1024 * 1024), 262144);
    split_kernel<<<1024, 256>>>((const float4*)Wp, (__nv_bfloat162*)Wph, (__nv_bfloat162*)Wpl, 262144);
    concat_bias<<<3, 1024>>>(bq, bk, bv, bqkv);

    // fused QKV projection -> split bf16 (q pre-scaled by 0.125)
    gemm_bf16s<<<dim3(QKV_DIM / 128, T_SEQ / 128), 256, GEMM_SMEM>>>(
        xh, xl, Wh, Wl, bqkv, nullptr, qkvh, qkvl, QKV_DIM, C_DIM, 1);

    // attention -> split bf16 y
    attn_mma<<<dim3(T_SEQ / 64, NHEAD), 128, ATTN_SMEM>>>(qkvh, qkvl, yh, yl);

    // output projection -> fp32 out
    gemm_bf16s<<<dim3(C_DIM / 128, T_SEQ / 128), 256, GEMM_SMEM>>>(
        yh, yl, Wph, Wpl, bp, out, nullptr, nullptr, C_DIM, C_DIM, 0);
}